// round 3
// baseline (speedup 1.0000x reference)
#include <cuda_runtime.h>
#include <math.h>

// Sinkhorn approximate EMD: B=8, N=2048, 3D points, 50 iterations.
// R3: ELL-sparse K/K^T (cutoff K>=1e-30, ~4.5% density), built in ONE kernel
// (no count/scan passes), then ONE persistent kernel runs all 100 Sinkhorn
// half-iterations + epilogue. One 8-CTA cluster per batch; barrier.cluster
// replaces kernel launches. Deterministic fixed-order reductions.

#define BB 8
#define NN 2048
#define NROWS (BB * NN)            // 16384
#define RSTRIDE 512                // max nnz per row (avg ~92, max ~300)
#define D2CUT 0.690776f            // -ln(1e-30)/100
#define CL 8                       // CTAs per cluster (= per batch)
#define RPC (NN / CL)              // rows per CTA in persistent kernel: 256

// ELL storage: entry = (float val, uint col) packed as 2 uint words.
__device__ unsigned g_ell[2][(size_t)NROWS * RSTRIDE * 2];   // 268 MB
__device__ unsigned g_cnt[2][NROWS];
__device__ float    g_expu[NROWS], g_expv[NROWS];
__device__ float    g_part[BB * CL];

#define CLUSTER_SYNC() do {                                              \
    asm volatile("barrier.cluster.arrive.aligned;" ::: "memory");        \
    asm volatile("barrier.cluster.wait.aligned;"   ::: "memory");        \
} while (0)

// ---------------------------------------------------------------------------
// Build ELL for both matrices in one launch.
// grid = 2 * NROWS/16 blocks; 512 threads; warp-per-row; ballot compaction.
// m=0: K rows are x1 points vs x2; m=1: K^T rows are x2 points vs x1.
__global__ __launch_bounds__(512) void build_kernel(const float* __restrict__ x1,
                                                    const float* __restrict__ x2) {
    __shared__ float sx[NN * 3];
    int m    = blockIdx.x >> 10;            // 0..1
    int rblk = blockIdx.x & 1023;           // 0..1023  (16 rows each)
    int b    = rblk >> 7;                   // batch

    const float* xa = m ? x2 : x1;
    const float* xb = m ? x1 : x2;
    const float* xbp = xb + (size_t)b * NN * 3;
    for (int t = threadIdx.x; t < NN * 3; t += 512) sx[t] = xbp[t];
    __syncthreads();

    int warp = threadIdx.x >> 5, lane = threadIdx.x & 31;
    int row  = rblk * 16 + warp;            // global row (includes batch)
    const float* ap = xa + (size_t)row * 3;
    float ax = ap[0], ay = ap[1], az = ap[2];

    unsigned* erow = g_ell[m] + (size_t)row * RSTRIDE * 2;
    unsigned base = 0;
    for (int c0 = 0; c0 < NN; c0 += 32) {
        int c = c0 + lane;
        float dx = ax - sx[3 * c];
        float dy = ay - sx[3 * c + 1];
        float dz = az - sx[3 * c + 2];
        float d2 = fmaf(dx, dx, fmaf(dy, dy, dz * dz));
        bool p = d2 < D2CUT;
        unsigned mk = __ballot_sync(0xffffffffu, p);
        if (p) {
            unsigned idx = base + __popc(mk & ((1u << lane) - 1u));
            if (idx < RSTRIDE) {
                uint2 e;
                e.x = __float_as_uint(__expf(-100.0f * d2));
                e.y = (unsigned)c;
                *(uint2*)(erow + idx * 2) = e;
            }
        }
        base += __popc(mk);
    }
    if (lane == 0) g_cnt[m][row] = (base < RSTRIDE) ? base : RSTRIDE;
}

// ---------------------------------------------------------------------------
// Persistent kernel: all 100 half-iterations + EMD epilogue.
// grid = 64 CTAs, cluster 8 (one cluster per batch), 1024 threads.
__global__ __cluster_dims__(CL, 1, 1) __launch_bounds__(1024, 1)
void sink_persist_kernel(float* __restrict__ out, float logm) {
    __shared__ float sev[NN];
    __shared__ float red[32];

    int cta   = blockIdx.x;
    int batch = cta >> 3;
    int crank = cta & (CL - 1);
    int t = threadIdx.x, warp = t >> 5, lane = t & 31;
    int rowbase = batch * NN + crank * RPC;   // this CTA's 256 rows (global idx)

    // ---- 100 Sinkhorn half-iterations ----
    for (int half = 0; half < 100; ++half) {
        int m = half & 1;   // 0: u update (K, reads expv); 1: v update (K^T, reads expu)

        // stage source exp-vector (v0 = 0 -> exp = 1 on first pass)
        if (half == 0) {
            ((float2*)sev)[t] = make_float2(1.0f, 1.0f);
        } else {
            const float* src = (m ? g_expu : g_expv) + batch * NN;
            ((float2*)sev)[t] = ((const float2*)src)[t];
        }
        __syncthreads();

        // 8 rows per warp (32 warps x 8 = 256 rows)
        #pragma unroll 1
        for (int rr = 0; rr < RPC / 32; ++rr) {
            int row = rowbase + warp * (RPC / 32) + rr;
            unsigned nnz = g_cnt[m][row];
            const uint4* ep = (const uint4*)(g_ell[m] + (size_t)row * RSTRIDE * 2);

            float acc = 0.0f;
            for (unsigned i = lane; 2 * i < nnz; i += 32) {
                uint4 e = ep[i];                       // two packed entries
                acc += __uint_as_float(e.x) * sev[e.y];
                if (2 * i + 1 < nnz)
                    acc += __uint_as_float(e.z) * sev[e.w];
            }
            #pragma unroll
            for (int o = 16; o; o >>= 1) acc += __shfl_down_sync(0xffffffffu, acc, o);

            if (lane == 0) {
                float ev = __expf(logm - __logf(acc + 1e-8f));
                if (m) g_expv[row] = ev; else g_expu[row] = ev;
            }
        }
        CLUSTER_SYNC();   // release writes / acquire for next phase
    }

    // ---- EMD epilogue: emd_b = -1/100 * sum_ij K * ln(K) * e^u_i * e^v_j ----
    ((float2*)sev)[t] = ((const float2*)(g_expv + batch * NN))[t];
    __syncthreads();

    float acc = 0.0f;
    #pragma unroll 1
    for (int rr = 0; rr < RPC / 32; ++rr) {
        int row = rowbase + warp * (RPC / 32) + rr;
        unsigned nnz = g_cnt[0][row];
        float eu = g_expu[row];
        const uint4* ep = (const uint4*)(g_ell[0] + (size_t)row * RSTRIDE * 2);

        float racc = 0.0f;
        for (unsigned i = lane; 2 * i < nnz; i += 32) {
            uint4 e = ep[i];
            float k0 = __uint_as_float(e.x);
            racc += k0 * __logf(k0) * sev[e.y];
            if (2 * i + 1 < nnz) {
                float k1 = __uint_as_float(e.z);
                racc += k1 * __logf(k1) * sev[e.w];
            }
        }
        acc += racc * eu;
    }
    // block reduce (fixed order)
    #pragma unroll
    for (int o = 16; o; o >>= 1) acc += __shfl_down_sync(0xffffffffu, acc, o);
    if (lane == 0) red[warp] = acc;
    __syncthreads();
    if (warp == 0) {
        float s = red[lane];
        #pragma unroll
        for (int o = 16; o; o >>= 1) s += __shfl_down_sync(0xffffffffu, s, o);
        if (lane == 0) g_part[cta] = s;
    }
    CLUSTER_SYNC();

    if (crank == 0 && t == 0) {
        float s = 0.0f;
        #pragma unroll
        for (int k = 0; k < CL; ++k) s += g_part[batch * CL + k];
        out[batch] = -s * 0.01f;   // d2 = -ln(K)/100
    }
}

// ---------------------------------------------------------------------------
extern "C" void kernel_launch(void* const* d_in, const int* in_sizes, int n_in,
                              void* d_out, int out_size) {
    (void)in_sizes; (void)n_in; (void)out_size;
    const float* x1 = (const float*)d_in[0];
    const float* x2 = (const float*)d_in[1];
    float* out = (float*)d_out;

    const float logm = logf(1.0f / 2048.0f + 1e-8f);

    build_kernel<<<2048, 512>>>(x1, x2);
    sink_persist_kernel<<<BB * CL, 1024>>>(out, logm);
}

// round 4
// speedup vs baseline: 1.4664x; 1.4664x over previous
#include <cuda_runtime.h>
#include <math.h>

// Sinkhorn approximate EMD: B=8, N=2048, 3D points, 50 iterations.
// R4: ELL-sparse (cutoff K>=1e-30, ~5% density) with SPLIT streams
// (fp32 vals / u16 cols / fp32 K*lnK), rows padded to 32-entry multiples.
// One build launch + one persistent launch (cluster of 8 CTAs per batch,
// barrier.cluster between half-iterations). Mainloop: 8 lanes per row,
// 4 concurrent rows per warp, metadata in smem -> high MLP, short reduces.

#define BB 8
#define NN 2048
#define NROWS (BB * NN)            // 16384
#define RSTRIDE 512                // padded max nnz per row (avg ~100, max ~330)
#define D2CUT 0.690776f            // -ln(1e-30)/100
#define CL 8                       // CTAs per cluster (= per batch)
#define RPC (NN / CL)              // rows per CTA: 256

__device__ float          g_vals[2][(size_t)NROWS * RSTRIDE];  // 67 MB
__device__ unsigned short g_cols[2][(size_t)NROWS * RSTRIDE];  // 34 MB
__device__ float          g_wv  [(size_t)NROWS * RSTRIDE];     // K*lnK for K (epilogue)
__device__ unsigned char  g_it  [2][NROWS];                    // ceil(nnz/32) iter counts
__device__ float          g_expu[NROWS], g_expv[NROWS];
__device__ float          g_part[BB * CL];

#define CLUSTER_SYNC() do {                                              \
    asm volatile("barrier.cluster.arrive.aligned;" ::: "memory");        \
    asm volatile("barrier.cluster.wait.aligned;"   ::: "memory");        \
} while (0)

// ---------------------------------------------------------------------------
// Build both ELL matrices. grid = 2048 blocks x 512 thr; warp per row.
// m=0: K rows = x1 vs x2 cols; m=1: K^T rows = x2 vs x1 cols.
__global__ __launch_bounds__(512) void build_kernel(const float* __restrict__ x1,
                                                    const float* __restrict__ x2) {
    __shared__ float sx[NN * 3];
    int m    = blockIdx.x >> 10;
    int rblk = blockIdx.x & 1023;           // 16 rows per block
    int b    = rblk >> 7;

    const float* xa = m ? x2 : x1;
    const float* xb = m ? x1 : x2;
    const float* xbp = xb + (size_t)b * NN * 3;
    for (int t = threadIdx.x; t < NN * 3; t += 512) sx[t] = xbp[t];
    __syncthreads();

    int warp = threadIdx.x >> 5, lane = threadIdx.x & 31;
    int row  = rblk * 16 + warp;
    const float* ap = xa + (size_t)row * 3;
    float ax = ap[0], ay = ap[1], az = ap[2];

    float*          vrow = g_vals[m] + (size_t)row * RSTRIDE;
    unsigned short* crow = g_cols[m] + (size_t)row * RSTRIDE;
    float*          wrow = g_wv      + (size_t)row * RSTRIDE;

    unsigned base = 0;
    for (int c0 = 0; c0 < NN; c0 += 32) {
        int c = c0 + lane;
        float dx = ax - sx[3 * c];
        float dy = ay - sx[3 * c + 1];
        float dz = az - sx[3 * c + 2];
        float d2 = fmaf(dx, dx, fmaf(dy, dy, dz * dz));
        bool p = d2 < D2CUT;
        unsigned mk = __ballot_sync(0xffffffffu, p);
        if (p) {
            unsigned idx = base + __popc(mk & ((1u << lane) - 1u));
            if (idx < RSTRIDE) {
                float k = __expf(-100.0f * d2);
                vrow[idx] = k;
                crow[idx] = (unsigned short)c;
                if (m == 0) wrow[idx] = k * (-100.0f * d2);   // K * lnK (exact arg)
            }
        }
        base += __popc(mk);
    }
    unsigned nnz = (base < RSTRIDE) ? base : RSTRIDE;
    unsigned pad = (nnz + 31u) & ~31u;
    for (unsigned idx = nnz + lane; idx < pad; idx += 32) {
        vrow[idx] = 0.0f; crow[idx] = 0;
        if (m == 0) wrow[idx] = 0.0f;
    }
    if (lane == 0) g_it[m][row] = (unsigned char)(pad >> 5);
}

// ---------------------------------------------------------------------------
// Persistent kernel: 100 half-iterations + epilogue.
// grid = 64 CTAs (cluster 8 = one batch), 1024 threads.
// Work split: 8 lanes per row, 4 rows per warp per pass, 2 passes (256 rows).
__global__ __cluster_dims__(CL, 1, 1) __launch_bounds__(1024, 1)
void sink_persist_kernel(float* __restrict__ out, float logm) {
    __shared__ float sev[NN];
    __shared__ unsigned char sit[2][RPC];
    __shared__ float red[32];

    int cta   = blockIdx.x;
    int batch = cta >> 3;
    int crank = cta & (CL - 1);
    int t = threadIdx.x, warp = t >> 5, lane = t & 31;
    int g  = lane >> 3;            // row group within warp: 0..3
    int gl = lane & 7;             // lane within group
    int rowbase = batch * NN + crank * RPC;

    // preload per-row iteration counts (iteration-invariant)
    for (int i = t; i < RPC; i += 1024) {
        sit[0][i] = g_it[0][rowbase + i];
        sit[1][i] = g_it[1][rowbase + i];
    }
    // local row indices this thread owns (pass 0 / pass 1)
    int rl0 = warp * 8 + g;        // 0..255 (first 4 rows of warp's 8)
    int rl1 = warp * 8 + 4 + g;
    __syncthreads();

    // ---- 100 Sinkhorn half-iterations ----
    for (int half = 0; half < 100; ++half) {
        int m = half & 1;  // 0: u update (K, reads expv) ; 1: v update (K^T, reads expu)

        if (half == 0) {
            ((float2*)sev)[t] = make_float2(1.0f, 1.0f);   // exp(v0) = 1
        } else {
            const float* src = (m ? g_expu : g_expv) + batch * NN;
            ((float2*)sev)[t] = ((const float2*)src)[t];
        }
        __syncthreads();

        float nv0, nv1;
        #pragma unroll
        for (int p = 0; p < 2; ++p) {
            int rl  = p ? rl1 : rl0;
            int row = rowbase + rl;
            int iters = sit[m][rl];
            const float4*   vp = (const float4*)(g_vals[m] + (size_t)row * RSTRIDE) + gl;
            const ushort4*  cp = (const ushort4*)(g_cols[m] + (size_t)row * RSTRIDE) + gl;

            float acc = 0.0f;
            #pragma unroll 2
            for (int i = 0; i < iters; ++i) {
                float4  v = vp[i * 8];
                ushort4 c = cp[i * 8];
                acc += v.x * sev[c.x] + v.y * sev[c.y]
                     + v.z * sev[c.z] + v.w * sev[c.w];
            }
            // reduce within 8-lane group
            acc += __shfl_xor_sync(0xffffffffu, acc, 4);
            acc += __shfl_xor_sync(0xffffffffu, acc, 2);
            acc += __shfl_xor_sync(0xffffffffu, acc, 1);
            if (p) nv1 = acc; else nv0 = acc;
        }

        if (gl == 0) {
            float e0 = __expf(logm - __logf(nv0 + 1e-8f));
            float e1 = __expf(logm - __logf(nv1 + 1e-8f));
            float* dst = m ? g_expv : g_expu;
            dst[rowbase + rl0] = e0;
            dst[rowbase + rl1] = e1;
        }
        CLUSTER_SYNC();   // cluster-scope release/acquire between phases
    }

    // ---- epilogue: emd_b = -(1/100) * sum_ij (K lnK)_ij * e^u_i * e^v_j ----
    ((float2*)sev)[t] = ((const float2*)(g_expv + batch * NN))[t];
    __syncthreads();

    float acc = 0.0f;
    #pragma unroll
    for (int p = 0; p < 2; ++p) {
        int rl  = p ? rl1 : rl0;
        int row = rowbase + rl;
        int iters = sit[0][rl];
        float eu = g_expu[row];
        const float4*  wp = (const float4*)(g_wv + (size_t)row * RSTRIDE) + gl;
        const ushort4* cp = (const ushort4*)(g_cols[0] + (size_t)row * RSTRIDE) + gl;

        float racc = 0.0f;
        #pragma unroll 2
        for (int i = 0; i < iters; ++i) {
            float4  w = wp[i * 8];
            ushort4 c = cp[i * 8];
            racc += w.x * sev[c.x] + w.y * sev[c.y]
                  + w.z * sev[c.z] + w.w * sev[c.w];
        }
        acc += racc * eu;
    }
    // fixed-order block reduce
    #pragma unroll
    for (int o = 16; o; o >>= 1) acc += __shfl_down_sync(0xffffffffu, acc, o);
    if (lane == 0) red[warp] = acc;
    __syncthreads();
    if (warp == 0) {
        float s = red[lane];
        #pragma unroll
        for (int o = 16; o; o >>= 1) s += __shfl_down_sync(0xffffffffu, s, o);
        if (lane == 0) g_part[cta] = s;
    }
    CLUSTER_SYNC();

    if (crank == 0 && t == 0) {
        float s = 0.0f;
        #pragma unroll
        for (int k = 0; k < CL; ++k) s += g_part[batch * CL + k];
        out[batch] = -s * 0.01f;     // cost = -lnK / 100
    }
}

// ---------------------------------------------------------------------------
extern "C" void kernel_launch(void* const* d_in, const int* in_sizes, int n_in,
                              void* d_out, int out_size) {
    (void)in_sizes; (void)n_in; (void)out_size;
    const float* x1 = (const float*)d_in[0];
    const float* x2 = (const float*)d_in[1];
    float* out = (float*)d_out;

    const float logm = logf(1.0f / 2048.0f + 1e-8f);

    build_kernel<<<2048, 512>>>(x1, x2);
    sink_persist_kernel<<<BB * CL, 1024>>>(out, logm);
}

// round 5
// speedup vs baseline: 1.4680x; 1.0011x over previous
#include <cuda_runtime.h>
#include <math.h>

// Sinkhorn approximate EMD: B=8, N=2048, 3D points, 50 iterations.
// R5: ELL-sparse with (val,col) PACKED into one u32 (11-bit col in the low
// mantissa bits, rel err <=1.2e-4). 16 CTAs per batch (128 CTAs ~ all SMs),
// software release/acquire barrier per batch instead of clusters, dynamic
// row scheduling inside each CTA (smem atomic) to kill nnz imbalance.

#define BB 8
#define NN 2048
#define NROWS (BB * NN)          // 16384
#define RSTRIDE 512              // padded max nnz per row (avg ~100, max ~340)
#define D2CUT 0.690776f          // -ln(1e-30)/100
#define CPB 16                   // CTAs per batch
#define RPC (NN / CPB)           // 128 rows per CTA
#define TPP 512                  // threads in persistent kernel

__device__ unsigned      g_pk[2][(size_t)NROWS * RSTRIDE];  // packed K / K^T (64 MB)
__device__ unsigned      g_pw[(size_t)NROWS * RSTRIDE];     // packed K*lnK   (32 MB)
__device__ unsigned char g_it[2][NROWS];                    // ceil(nnz/32)
__device__ float g_expu[NROWS], g_expv[NROWS];
__device__ float g_part[BB * CPB];
__device__ unsigned g_bar[BB];

// pack: round-to-nearest on the kept 12 mantissa bits, low 11 bits = column
__device__ __forceinline__ unsigned packf(float f, unsigned c) {
    return ((__float_as_uint(f) + 0x400u) & 0xFFFFF800u) | c;
}

__device__ __forceinline__ void bar_arrive(unsigned* p) {
    asm volatile("red.release.gpu.add.u32 [%0], 1;" :: "l"(p) : "memory");
}
__device__ __forceinline__ unsigned bar_peek(unsigned* p) {
    unsigned v;
    asm volatile("ld.acquire.gpu.u32 %0, [%1];" : "=r"(v) : "l"(p) : "memory");
    return v;
}

// ---------------------------------------------------------------------------
__global__ void init_kernel() {
    if (threadIdx.x < BB) g_bar[threadIdx.x] = 0;
}

// ---------------------------------------------------------------------------
// Build both packed ELL matrices. 2048 blocks x 512 thr; warp per row.
// m=0: K rows = x1 vs x2 cols; m=1: K^T rows = x2 vs x1 cols.
__global__ __launch_bounds__(512) void build_kernel(const float* __restrict__ x1,
                                                    const float* __restrict__ x2) {
    __shared__ float sx[NN * 3];
    int m    = blockIdx.x >> 10;
    int rblk = blockIdx.x & 1023;           // 16 rows per block
    int b    = rblk >> 7;

    const float* xa = m ? x2 : x1;
    const float* xb = m ? x1 : x2;
    const float* xbp = xb + (size_t)b * NN * 3;
    for (int t = threadIdx.x; t < NN * 3; t += 512) sx[t] = xbp[t];
    __syncthreads();

    int warp = threadIdx.x >> 5, lane = threadIdx.x & 31;
    int row  = rblk * 16 + warp;
    const float* ap = xa + (size_t)row * 3;
    float ax = ap[0], ay = ap[1], az = ap[2];

    unsigned* krow = g_pk[m] + (size_t)row * RSTRIDE;
    unsigned* wrow = g_pw    + (size_t)row * RSTRIDE;

    unsigned base = 0;
    for (int c0 = 0; c0 < NN; c0 += 32) {
        int c = c0 + lane;
        float dx = ax - sx[3 * c];
        float dy = ay - sx[3 * c + 1];
        float dz = az - sx[3 * c + 2];
        float d2 = fmaf(dx, dx, fmaf(dy, dy, dz * dz));
        bool p = d2 < D2CUT;
        unsigned mk = __ballot_sync(0xffffffffu, p);
        if (p) {
            unsigned idx = base + __popc(mk & ((1u << lane) - 1u));
            if (idx < RSTRIDE) {
                float k = __expf(-100.0f * d2);
                krow[idx] = packf(k, (unsigned)c);
                if (m == 0) wrow[idx] = packf(k * (-100.0f * d2), (unsigned)c);
            }
        }
        base += __popc(mk);
    }
    unsigned nnz = (base < RSTRIDE) ? base : RSTRIDE;
    unsigned pad = (nnz + 31u) & ~31u;
    for (unsigned idx = nnz + lane; idx < pad; idx += 32) {
        krow[idx] = 0u;
        if (m == 0) wrow[idx] = 0u;
    }
    if (lane == 0) g_it[m][row] = (unsigned char)(pad >> 5);
}

// ---------------------------------------------------------------------------
// Persistent kernel: 100 half-iterations + epilogue.
// grid = 128 CTAs (16 per batch), 512 threads, 8-lane groups, dynamic rows.
__global__ __launch_bounds__(TPP, 1)
void sink_persist_kernel(float* __restrict__ out, float logm) {
    __shared__ float sev[NN];
    __shared__ unsigned char sit[2][RPC];
    __shared__ float red[16];
    __shared__ int ctr;

    int cta   = blockIdx.x;
    int batch = cta >> 4;
    int crank = cta & (CPB - 1);
    int t = threadIdx.x, warp = t >> 5, lane = t & 31;
    int gl = lane & 7;                       // lane within 8-lane group
    unsigned gmask = 0xFFu << (lane & 24);   // this group's lane mask
    int rowbase = batch * NN + crank * RPC;

    for (int i = t; i < RPC; i += TPP) {
        sit[0][i] = g_it[0][rowbase + i];
        sit[1][i] = g_it[1][rowbase + i];
    }
    unsigned target = 0;

    // ---- 100 Sinkhorn half-iterations ----
    for (int half = 0; half < 100; ++half) {
        int m = half & 1;  // 0: u update (K, reads expv); 1: v update (K^T, reads expu)

        if (half == 0) {
            ((float4*)sev)[t] = make_float4(1.f, 1.f, 1.f, 1.f);   // exp(v0)=1
        } else {
            const float4* src = (const float4*)((m ? g_expu : g_expv) + batch * NN);
            ((float4*)sev)[t] = __ldcg(src + t);
        }
        if (t == 0) ctr = 0;
        __syncthreads();

        // dynamic row pop: 64 groups x (RPC/64 = 2 rows avg)
        for (;;) {
            int r;
            if (gl == 0) r = atomicAdd(&ctr, 1);
            r = __shfl_sync(gmask, r, 0, 8);
            if (r >= RPC) break;

            int row = rowbase + r;
            int iters = sit[m][r];
            const uint4* ep = (const uint4*)(g_pk[m] + (size_t)row * RSTRIDE) + gl;

            float acc = 0.0f;
            #pragma unroll 2
            for (int i = 0; i < iters; ++i) {
                uint4 e = ep[i * 8];
                acc += __uint_as_float(e.x & 0xFFFFF800u) * sev[e.x & 0x7FFu]
                     + __uint_as_float(e.y & 0xFFFFF800u) * sev[e.y & 0x7FFu]
                     + __uint_as_float(e.z & 0xFFFFF800u) * sev[e.z & 0x7FFu]
                     + __uint_as_float(e.w & 0xFFFFF800u) * sev[e.w & 0x7FFu];
            }
            acc += __shfl_xor_sync(gmask, acc, 4, 8);
            acc += __shfl_xor_sync(gmask, acc, 2, 8);
            acc += __shfl_xor_sync(gmask, acc, 1, 8);

            if (gl == 0) {
                float ev = __expf(logm - __logf(acc + 1e-8f));
                (m ? g_expv : g_expu)[row] = ev;
            }
        }
        __syncthreads();

        // per-batch software barrier (release arrive, acquire spin)
        target += CPB;
        if (t == 0) {
            bar_arrive(&g_bar[batch]);
            while (bar_peek(&g_bar[batch]) < target) __nanosleep(64);
        }
        __syncthreads();
    }

    // ---- epilogue: emd_b = -(1/100) * sum_ij (K lnK)_ij e^{u_i} e^{v_j} ----
    ((float4*)sev)[t] = __ldcg((const float4*)(g_expv + batch * NN) + t);
    __syncthreads();

    int g = t >> 3;                          // group id 0..63 (static rows!)
    float acc = 0.0f;
    for (int r = g; r < RPC; r += 64) {      // deterministic assignment
        int row = rowbase + r;
        int iters = sit[0][r];
        float eu = __ldcg(&g_expu[row]);
        const uint4* wp = (const uint4*)(g_pw + (size_t)row * RSTRIDE) + gl;

        float racc = 0.0f;
        #pragma unroll 2
        for (int i = 0; i < iters; ++i) {
            uint4 e = wp[i * 8];
            racc += __uint_as_float(e.x & 0xFFFFF800u) * sev[e.x & 0x7FFu]
                  + __uint_as_float(e.y & 0xFFFFF800u) * sev[e.y & 0x7FFu]
                  + __uint_as_float(e.z & 0xFFFFF800u) * sev[e.z & 0x7FFu]
                  + __uint_as_float(e.w & 0xFFFFF800u) * sev[e.w & 0x7FFu];
        }
        racc += __shfl_xor_sync(gmask, racc, 4, 8);
        racc += __shfl_xor_sync(gmask, racc, 2, 8);
        racc += __shfl_xor_sync(gmask, racc, 1, 8);
        if (gl == 0) acc += racc * eu;       // only group leader accumulates
    }
    // fixed-order block reduce (non-leaders hold 0 beyond their groups)
    #pragma unroll
    for (int o = 16; o; o >>= 1) acc += __shfl_down_sync(0xffffffffu, acc, o);
    if (lane == 0) red[warp] = acc;
    __syncthreads();
    if (warp == 0) {
        float s = (lane < 16) ? red[lane] : 0.0f;
        #pragma unroll
        for (int o = 8; o; o >>= 1) s += __shfl_down_sync(0xffffffffu, s, o);
        if (lane == 0) g_part[cta] = s;
    }
    __syncthreads();

    target += CPB;
    if (t == 0) {
        bar_arrive(&g_bar[batch]);
        if (crank == 0) {
            while (bar_peek(&g_bar[batch]) < target) __nanosleep(64);
            float s = 0.0f;
            #pragma unroll
            for (int k = 0; k < CPB; ++k) s += __ldcg(&g_part[batch * CPB + k]);
            out[batch] = -s * 0.01f;         // cost = -lnK / 100
        }
    }
}

// ---------------------------------------------------------------------------
extern "C" void kernel_launch(void* const* d_in, const int* in_sizes, int n_in,
                              void* d_out, int out_size) {
    (void)in_sizes; (void)n_in; (void)out_size;
    const float* x1 = (const float*)d_in[0];
    const float* x2 = (const float*)d_in[1];
    float* out = (float*)d_out;

    const float logm = logf(1.0f / 2048.0f + 1e-8f);

    init_kernel<<<1, 32>>>();
    build_kernel<<<2048, 512>>>(x1, x2);
    sink_persist_kernel<<<BB * CPB, TPP>>>(out, logm);
}

// round 6
// speedup vs baseline: 1.9150x; 1.3045x over previous
#include <cuda_runtime.h>
#include <math.h>

// Sinkhorn approximate EMD: B=8, N=2048, 3D points, 50 iterations.
// R6: SINGLE fused persistent kernel. Each CTA (16 per batch, 128 total,
// 1024 threads) builds its own CTA-private packed-ELL rows of K and K^T
// (val packed with 11-bit col in the mantissa LSBs), then runs 100 Sinkhorn
// half-iterations with one row per 8-lane group (no pops, no sequential
// rows) and a tight gpu-scope software barrier per half. Epilogue
// recomputes k*ln(k) on the fly. Barrier counters self-reset for replays.

#define BB 8
#define NN 2048
#define NROWS (BB * NN)          // 16384
#define RSTRIDE 512              // padded max nnz per row (avg ~104, max ~340)
#define D2CUT 0.690776f          // -ln(1e-30)/100
#define CPB 16                   // CTAs per batch
#define RPC 128                  // rows per CTA (NN / CPB)
#define TPB 1024                 // 128 groups x 8 lanes

__device__ unsigned g_pk[2][(size_t)NROWS * RSTRIDE];   // packed K / K^T (64 MB)
__device__ float    g_expu[NROWS], g_expv[NROWS];
__device__ float    g_part[BB * CPB];
__device__ unsigned g_bar[BB];   // zero-initialized at load; self-reset per call

// pack: round-to-nearest on kept 21 high bits, low 11 bits = column index
__device__ __forceinline__ unsigned packf(float f, unsigned c) {
    return ((__float_as_uint(f) + 0x400u) & 0xFFFFF800u) | c;
}

__device__ __forceinline__ void bar_arrive(unsigned* p) {
    asm volatile("red.release.gpu.add.u32 [%0], 1;" :: "l"(p) : "memory");
}
__device__ __forceinline__ unsigned bar_peek(unsigned* p) {
    unsigned v;
    asm volatile("ld.acquire.gpu.u32 %0, [%1];" : "=r"(v) : "l"(p) : "memory");
    return v;
}

// ---------------------------------------------------------------------------
__global__ __launch_bounds__(TPB, 1)
void fused_sinkhorn(const float* __restrict__ x1, const float* __restrict__ x2,
                    float* __restrict__ out, float logm) {
    __shared__ float sxbuf[NN * 3];          // build staging; first 2048 reused as sev
    __shared__ unsigned char sit[2][RPC];    // per-row uint4-iteration counts
    __shared__ float red[32];
    float* sev = sxbuf;

    int cta = blockIdx.x, batch = cta >> 4, crank = cta & (CPB - 1);
    int t = threadIdx.x, warp = t >> 5, lane = t & 31;
    int rowbase = batch * NN + crank * RPC;

    // ===== inline build: CTA-private ELL rows of K (m=0) and K^T (m=1) =====
    #pragma unroll 1
    for (int m = 0; m < 2; ++m) {
        const float* rowpts = m ? x2 : x1;
        const float* colpts = m ? x1 : x2;
        const float* cp = colpts + (size_t)batch * NN * 3;
        for (int i = t; i < NN * 3; i += TPB) sxbuf[i] = cp[i];
        __syncthreads();

        #pragma unroll 1
        for (int rr = 0; rr < RPC / 32; ++rr) {      // 4 rows per warp
            int r   = warp * (RPC / 32) + rr;
            int row = rowbase + r;
            const float* ap = rowpts + (size_t)row * 3;
            float ax = ap[0], ay = ap[1], az = ap[2];
            unsigned* krow = g_pk[m] + (size_t)row * RSTRIDE;

            unsigned base = 0;
            for (int c0 = 0; c0 < NN; c0 += 32) {
                int c = c0 + lane;
                float dx = ax - sxbuf[3 * c];
                float dy = ay - sxbuf[3 * c + 1];
                float dz = az - sxbuf[3 * c + 2];
                float d2 = fmaf(dx, dx, fmaf(dy, dy, dz * dz));
                bool p = d2 < D2CUT;
                unsigned mk = __ballot_sync(0xffffffffu, p);
                if (p) {
                    unsigned idx = base + __popc(mk & ((1u << lane) - 1u));
                    if (idx < RSTRIDE)
                        krow[idx] = packf(__expf(-100.0f * d2), (unsigned)c);
                }
                base += __popc(mk);
            }
            unsigned nnz = (base < RSTRIDE) ? base : RSTRIDE;
            unsigned pad = (nnz + 31u) & ~31u;
            for (unsigned idx = nnz + lane; idx < pad; idx += 32) krow[idx] = 0u;
            if (lane == 0) sit[m][r] = (unsigned char)(pad >> 5);
        }
        __syncthreads();
    }

    // ===== 100 Sinkhorn half-iterations =====
    int g = t >> 3, gl = t & 7;              // 128 groups, group g owns local row g
    int myrow = rowbase + g;
    unsigned target = 0;
    unsigned* barp = &g_bar[batch];

    #pragma unroll 1
    for (int half = 0; half < 100; ++half) {
        int m = half & 1;   // 0: u update (K, reads expv); 1: v update (K^T, reads expu)

        if (t < NN / 4) {
            float4 v;
            if (half == 0) v = make_float4(1.f, 1.f, 1.f, 1.f);   // exp(v0)=1
            else v = __ldcg((const float4*)((m ? g_expu : g_expv) + batch * NN) + t);
            ((float4*)sev)[t] = v;
        }
        __syncthreads();

        int iters = sit[m][g];
        const uint4* ep = (const uint4*)(g_pk[m] + (size_t)myrow * RSTRIDE) + gl;
        float acc = 0.0f;
        #pragma unroll 2
        for (int i = 0; i < iters; ++i) {
            uint4 e = ep[(size_t)i * 8];
            acc += __uint_as_float(e.x & 0xFFFFF800u) * sev[e.x & 0x7FFu]
                 + __uint_as_float(e.y & 0xFFFFF800u) * sev[e.y & 0x7FFu]
                 + __uint_as_float(e.z & 0xFFFFF800u) * sev[e.z & 0x7FFu]
                 + __uint_as_float(e.w & 0xFFFFF800u) * sev[e.w & 0x7FFu];
        }
        acc += __shfl_xor_sync(0xffffffffu, acc, 4);
        acc += __shfl_xor_sync(0xffffffffu, acc, 2);
        acc += __shfl_xor_sync(0xffffffffu, acc, 1);

        if (gl == 0) {
            float ev = __expf(logm - __logf(acc + 1e-8f));
            __stcg((m ? g_expv : g_expu) + myrow, ev);
        }
        __syncthreads();                      // all stores done before arrive

        target += CPB;
        if (t == 0) {
            bar_arrive(barp);
            while (bar_peek(barp) < target) { }   // tight spin, 1 thread/CTA
        }
        __syncthreads();
    }

    // ===== epilogue: emd_b = -(1/100) * sum_ij k ln(k) e^{u_i} e^{v_j} =====
    if (t < NN / 4)
        ((float4*)sev)[t] = __ldcg((const float4*)(g_expv + batch * NN) + t);
    __syncthreads();

    {
        int iters = sit[0][g];
        float eu = __ldcg(g_expu + myrow);
        const uint4* ep = (const uint4*)(g_pk[0] + (size_t)myrow * RSTRIDE) + gl;
        float racc = 0.0f;
        #pragma unroll 2
        for (int i = 0; i < iters; ++i) {
            uint4 e = ep[(size_t)i * 8];
            unsigned b;
            b = e.x & 0xFFFFF800u;
            if (b) { float k = __uint_as_float(b); racc += k * __logf(k) * sev[e.x & 0x7FFu]; }
            b = e.y & 0xFFFFF800u;
            if (b) { float k = __uint_as_float(b); racc += k * __logf(k) * sev[e.y & 0x7FFu]; }
            b = e.z & 0xFFFFF800u;
            if (b) { float k = __uint_as_float(b); racc += k * __logf(k) * sev[e.z & 0x7FFu]; }
            b = e.w & 0xFFFFF800u;
            if (b) { float k = __uint_as_float(b); racc += k * __logf(k) * sev[e.w & 0x7FFu]; }
        }
        racc += __shfl_xor_sync(0xffffffffu, racc, 4);
        racc += __shfl_xor_sync(0xffffffffu, racc, 2);
        racc += __shfl_xor_sync(0xffffffffu, racc, 1);

        float acc = (gl == 0) ? racc * eu : 0.0f;   // group leader carries row sum
        #pragma unroll
        for (int o = 16; o; o >>= 1) acc += __shfl_down_sync(0xffffffffu, acc, o);
        if (lane == 0) red[warp] = acc;
        __syncthreads();
        if (warp == 0) {
            float s = red[lane];
            #pragma unroll
            for (int o = 16; o; o >>= 1) s += __shfl_down_sync(0xffffffffu, s, o);
            if (lane == 0) __stcg(&g_part[cta], s);
        }
    }
    __syncthreads();

    target += CPB;
    if (t == 0) {
        bar_arrive(barp);
        if (crank == 0) {                      // only rank 0 waits; others exit
            while (bar_peek(barp) < target) { }
            float s = 0.0f;
            #pragma unroll
            for (int k = 0; k < CPB; ++k) s += __ldcg(&g_part[batch * CPB + k]);
            out[batch] = -s * 0.01f;           // cost = -ln(K)/100
            *barp = 0u;                        // reset for next graph replay
        }
    }
}

// ---------------------------------------------------------------------------
extern "C" void kernel_launch(void* const* d_in, const int* in_sizes, int n_in,
                              void* d_out, int out_size) {
    (void)in_sizes; (void)n_in; (void)out_size;
    const float* x1 = (const float*)d_in[0];
    const float* x2 = (const float*)d_in[1];
    float* out = (float*)d_out;

    const float logm = logf(1.0f / 2048.0f + 1e-8f);
    fused_sinkhorn<<<BB * CPB, TPB>>>(x1, x2, out, logm);
}